// round 3
// baseline (speedup 1.0000x reference)
#include <cuda_runtime.h>
#include <cuda_bf16.h>
#include <math.h>

// Problem constants (fixed by the dataset)
#define BB 8
#define NN 2000
#define CC 81
#define IOU_THR 0.5f
#define CLASS_OFFSET 100000.0f
#define CAP 96                  // per-(batch,class) bucket capacity (mean ~25, +14 sigma)

#define NBLK 296                // 2 blocks/SM on 148 SMs; all resident at launch
#define TPB 256
#define WPB (TPB / 32)
#define NWARPS (NBLK * WPB)     // 2368
#define NROWS (BB * NN)         // 16000
#define NTASK (BB * (CC - 1))   // 640 NMS tasks

// Output layout: concat of reference's 7-tuple, all float32
// (nms_reg, nms_cls, rcnn_reg_adj, probs, reg_out, cls_out, keep)
#define OFF0 0
#define OFF1 (BB*NN*4)
#define OFF2 (OFF1 + BB*NN*2)
#define OFF3 (OFF2 + BB*NN*4)
#define OFF4 (OFF3 + BB*NN*CC)
#define OFF5 (OFF4 + BB*NN*4)
#define OFF6 (OFF5 + BB*NN*CC)

// ---- scratch (device globals; no allocation allowed) ----
__device__ float4             g_offbox[NROWS];       // class-offset boxes (t,l,b,r)
__device__ int                g_cnt[BB*CC];          // bucket counters (zeroed for NEXT launch in phase 3)
__device__ unsigned long long g_bucket[BB*CC*CAP];   // composite keys per bucket
__device__ unsigned char      g_keep[NROWS];

// ---- software grid barrier state ----
__device__ unsigned          g_bar_count;
__device__ volatile unsigned g_bar_gen;

__device__ __forceinline__ void grid_barrier()
{
    __syncthreads();
    if (threadIdx.x == 0) {
        __threadfence();
        unsigned gen = g_bar_gen;
        if (atomicAdd(&g_bar_count, 1) == NBLK - 1) {
            g_bar_count = 0;
            __threadfence();
            g_bar_gen = gen + 1;
        } else {
            while (g_bar_gen == gen) { __nanosleep(64); }
            __threadfence();
        }
    }
    __syncthreads();
}

// reduction input may arrive as int32 or float32; handle both.
__device__ __forceinline__ float read_reduction(const void* p) {
    if (p == nullptr) return 16.0f;
    int iv = *(const int*)p;
    if (iv > 0 && iv < (1 << 20)) return (float)iv;
    return *(const float*)p;
}

__global__ __launch_bounds__(TPB)
void fused_kernel(const float* __restrict__ nms_reg,
                  const float* __restrict__ nms_cls,
                  const float* __restrict__ rcnn_reg,
                  const float* __restrict__ rcnn_cls,
                  const void* __restrict__ redp,
                  float* __restrict__ out)
{
    const int lane  = threadIdx.x & 31;
    const int wib   = threadIdx.x >> 5;                  // warp in block
    const int gwarp = blockIdx.x * WPB + wib;            // global warp id

    // =========================================================
    // Phase 1: per-row prep (softmax, argmax, boxes, buckets)
    // g_cnt is guaranteed zero on entry (module load / previous
    // launch's phase 3).
    // =========================================================
    for (int row = gwarp; row < NROWS; row += NWARPS) {
        const float* cl = rcnn_cls + (size_t)row * CC;
        float v0 = cl[lane];
        float v1 = cl[lane + 32];
        float v2 = (lane + 64 < CC) ? cl[lane + 64] : -INFINITY;

        float m = fmaxf(v0, fmaxf(v1, v2));
        #pragma unroll
        for (int o = 16; o; o >>= 1) m = fmaxf(m, __shfl_xor_sync(0xFFFFFFFFu, m, o));

        float e0 = expf(v0 - m);
        float e1 = expf(v1 - m);
        float e2 = (lane + 64 < CC) ? expf(v2 - m) : 0.0f;
        float s = e0 + e1 + e2;
        #pragma unroll
        for (int o = 16; o; o >>= 1) s += __shfl_xor_sync(0xFFFFFFFFu, s, o);

        float p0 = e0 / s, p1 = e1 / s, p2 = e2 / s;
        float* po = out + OFF3 + (size_t)row * CC;
        po[lane]      = p0;
        po[lane + 32] = p1;
        if (lane + 64 < CC) po[lane + 64] = p2;

        // argmax of probs, first-occurrence tie rule
        float bp = p0; int bi = lane;
        if (p1 > bp) { bp = p1; bi = lane + 32; }
        if (lane + 64 < CC && p2 > bp) { bp = p2; bi = lane + 64; }
        #pragma unroll
        for (int o = 16; o; o >>= 1) {
            float op = __shfl_xor_sync(0xFFFFFFFFu, bp, o);
            int   oi = __shfl_xor_sync(0xFFFFFFFFu, bi, o);
            if (op > bp || (op == bp && oi < bi)) { bp = op; bi = oi; }
        }

        if (lane == 0) {
            int b = row / NN, n = row % NN;
            int cls = bi;
            float red = read_reduction(redp);

            float4 nr = ((const float4*)nms_reg)[row];
            float rt = floorf(nr.x * red) / red;
            float rl = floorf(nr.y * red) / red;
            float rb = ceilf(nr.z * red) / red;
            float rr = ceilf(nr.w * red) / red;

            float4 rg = ((const float4*)rcnn_reg)[row];
            float at = rg.x + rt, al = rg.y + rl, ab = rg.z + rb, ar = rg.w + rr;

            float4 adj; adj.x = at; adj.y = al; adj.z = ab; adj.w = ar;
            ((float4*)(out + OFF2))[row] = adj;

            float off = (float)cls * CLASS_OFFSET;
            float4 ob; ob.x = at + off; ob.y = al + off; ob.z = ab + off; ob.w = ar + off;
            g_offbox[row] = ob;

            // passthrough copies
            ((float4*)(out + OFF0))[row] = nr;
            ((float2*)(out + OFF1))[row] = ((const float2*)nms_cls)[row];

            g_keep[row] = 0;

            if (cls != 0) {
                // composite key: score desc, idx asc (ascending u64 order)
                unsigned sb = __float_as_uint(bp);
                unsigned so = (sb & 0x80000000u) ? ~sb : (sb | 0x80000000u);
                unsigned sdesc = ~so;
                unsigned long long key = ((unsigned long long)sdesc << 32)
                                       | (unsigned long long)(unsigned)n;
                int bc = b * CC + cls;
                int pos = atomicAdd(&g_cnt[bc], 1);
                if (pos < CAP) g_bucket[(size_t)bc * CAP + pos] = key;
            }
        }
    }

    grid_barrier();

    // =========================================================
    // Phase 2: per-(batch,class) greedy NMS, one warp per task.
    // Cross-class IoU is exactly 0 due to CLASS_OFFSET, so
    // per-class greedy NMS in (score desc, idx asc) order is
    // identical to the reference's global greedy loop.
    // =========================================================
    {
        __shared__ unsigned long long s_raw [WPB][CAP];
        __shared__ float4             s_box [WPB][CAP];
        __shared__ unsigned short     s_sid [WPB][CAP];
        __shared__ unsigned char      s_keep[WPB][CAP];

        if (gwarp < NTASK) {
            int b = gwarp / (CC - 1);
            int c = gwarp % (CC - 1) + 1;
            int bc = b * CC + c;

            int n = g_cnt[bc];
            if (n > CAP) n = CAP;
            if (n > 0) {
                const unsigned long long* bk = g_bucket + (size_t)bc * CAP;
                for (int j = lane; j < n; j += 32) s_raw[wib][j] = bk[j];
                __syncwarp();

                // rank sort (keys unique via idx low bits -> perfect permutation)
                for (int j = lane; j < n; j += 32) {
                    unsigned long long kj = s_raw[wib][j];
                    int rank = 0;
                    for (int k = 0; k < n; k++) rank += (s_raw[wib][k] < kj);
                    int idx = (int)(kj & 0xFFFFFFFFu);
                    s_sid[wib][rank]  = (unsigned short)idx;
                    s_box[wib][rank]  = g_offbox[b * NN + idx];
                    s_keep[wib][rank] = 1;
                }
                __syncwarp();

                for (int i = 0; i < n - 1; i++) {
                    if (s_keep[wib][i]) {
                        float4 bi = s_box[wib][i];
                        float areai = (bi.z - bi.x) * (bi.w - bi.y);
                        for (int j = i + 1 + lane; j < n; j += 32) {
                            if (s_keep[wib][j]) {
                                float4 bj = s_box[wib][j];
                                float areaj = (bj.z - bj.x) * (bj.w - bj.y);
                                float it = fmaxf(bi.x, bj.x);
                                float il = fmaxf(bi.y, bj.y);
                                float ib = fminf(bi.z, bj.z);
                                float ir = fminf(bi.w, bj.w);
                                float inter = fmaxf(ib - it, 0.0f) * fmaxf(ir - il, 0.0f);
                                float uni = areai + areaj - inter;
                                float iou = inter / fmaxf(uni, 1e-9f);
                                if (iou > IOU_THR) s_keep[wib][j] = 0;
                            }
                        }
                    }
                    __syncwarp();
                }

                for (int j = lane; j < n; j += 32)
                    if (s_keep[wib][j]) g_keep[b * NN + (int)s_sid[wib][j]] = 1;
            }
        }
    }

    grid_barrier();

    // =========================================================
    // Phase 3: epilogue (masked outputs + keep) + counter reset
    // for the NEXT launch. probs row read should hit L2 (written
    // in phase 1, 5.2MB << 126MB L2).
    // =========================================================
    {
        int gtid = blockIdx.x * TPB + threadIdx.x;
        if (gtid < BB * CC) g_cnt[gtid] = 0;

        for (int row = gwarp; row < NROWS; row += NWARPS) {
            float k = g_keep[row] ? 1.0f : 0.0f;

            const float* po = out + OFF3 + (size_t)row * CC;
            float* co = out + OFF5 + (size_t)row * CC;
            float q0 = po[lane];
            float q1 = po[lane + 32];
            float q2 = (lane + 64 < CC) ? po[lane + 64] : 0.0f;
            co[lane]      = q0 * k;
            co[lane + 32] = q1 * k;
            if (lane + 64 < CC) co[lane + 64] = q2 * k;

            if (lane == 0) {
                float4 rg = ((const float4*)(out + OFF2))[row];
                rg.x *= k; rg.y *= k; rg.z *= k; rg.w *= k;
                ((float4*)(out + OFF4))[row] = rg;
                out[OFF6 + row] = k;
            }
        }
    }
}

extern "C" void kernel_launch(void* const* d_in, const int* in_sizes, int n_in,
                              void* d_out, int out_size)
{
    const float* nms_reg  = (const float*)d_in[0];
    const float* nms_cls  = (const float*)d_in[1];
    const float* rcnn_reg = (const float*)d_in[2];
    const float* rcnn_cls = (const float*)d_in[3];
    const void*  redp     = (n_in >= 5) ? d_in[4] : nullptr;
    float* out = (float*)d_out;
    (void)in_sizes; (void)out_size;

    fused_kernel<<<NBLK, TPB>>>(nms_reg, nms_cls, rcnn_reg, rcnn_cls, redp, out);
}

// round 4
// speedup vs baseline: 1.2983x; 1.2983x over previous
#include <cuda_runtime.h>
#include <cuda_bf16.h>
#include <math.h>

// Problem constants (fixed by the dataset)
#define BB 8
#define NN 2000
#define CC 81
#define IOU_THR 0.5f
#define CLASS_OFFSET 100000.0f
#define CAP 96                  // per-(batch,class) bucket capacity (mean ~25, +14 sigma)
#define NROWS (BB * NN)         // 16000
#define NTASK (BB * (CC - 1))   // 640 NMS tasks

// Output layout: concat of reference's 7-tuple, all float32
// (nms_reg, nms_cls, rcnn_reg_adj, probs, reg_out, cls_out, keep)
#define OFF0 0
#define OFF1 (BB*NN*4)
#define OFF2 (OFF1 + BB*NN*2)
#define OFF3 (OFF2 + BB*NN*4)
#define OFF4 (OFF3 + BB*NN*CC)
#define OFF5 (OFF4 + BB*NN*4)
#define OFF6 (OFF5 + BB*NN*CC)

// ---- scratch (device globals; zero-initialized at module load; no allocation) ----
__device__ int                g_cnt[BB*CC];          // bucket counters; nms resets after reading
__device__ unsigned long long g_bucket[BB*CC*CAP];   // composite keys per bucket

// reduction input may arrive as int32 or float32; handle both.
__device__ __forceinline__ float read_reduction(const void* p) {
    if (p == nullptr) return 16.0f;
    int iv = *(const int*)p;
    if (iv > 0 && iv < (1 << 20)) return (float)iv;
    return *(const float*)p;
}

// ============================================================
// Kernel 1: per-row prep, one warp per TWO rows (ILP x2).
//  - softmax over 81 classes -> probs out
//  - argmax (first-occurrence tie rule) -> class, score
//  - speculative outputs: cls_out = probs*k, reg_out = adj*k,
//    keep = k, with k = (cls != 0). NMS later zeroes the few
//    suppressed rows.
//  - append composite key to per-(b,class) bucket
// ============================================================
__global__ __launch_bounds__(256)
void prep_kernel(const float* __restrict__ nms_reg,
                 const float* __restrict__ nms_cls,
                 const float* __restrict__ rcnn_reg,
                 const float* __restrict__ rcnn_cls,
                 const void* __restrict__ redp,
                 float* __restrict__ out)
{
    const int gw   = (blockIdx.x * blockDim.x + threadIdx.x) >> 5;
    const int lane = threadIdx.x & 31;
    const int row0 = gw * 2;
    if (row0 >= NROWS) return;
    const int row1 = row0 + 1;

    const bool has2 = (lane < CC - 64);   // lane+64 < 81  -> lane < 17
    const float* cl0 = rcnn_cls + (size_t)row0 * CC;
    const float* cl1 = cl0 + CC;

    // 6 independent global loads in flight
    float a0 = cl0[lane];
    float a1 = cl0[lane + 32];
    float a2 = has2 ? cl0[lane + 64] : -INFINITY;
    float b0 = cl1[lane];
    float b1 = cl1[lane + 32];
    float b2 = has2 ? cl1[lane + 64] : -INFINITY;

    float mA = fmaxf(a0, fmaxf(a1, a2));
    float mB = fmaxf(b0, fmaxf(b1, b2));
    #pragma unroll
    for (int o = 16; o; o >>= 1) {
        mA = fmaxf(mA, __shfl_xor_sync(0xFFFFFFFFu, mA, o));
        mB = fmaxf(mB, __shfl_xor_sync(0xFFFFFFFFu, mB, o));
    }

    float eA0 = expf(a0 - mA), eA1 = expf(a1 - mA), eA2 = has2 ? expf(a2 - mA) : 0.0f;
    float eB0 = expf(b0 - mB), eB1 = expf(b1 - mB), eB2 = has2 ? expf(b2 - mB) : 0.0f;
    float sA = eA0 + eA1 + eA2;
    float sB = eB0 + eB1 + eB2;
    #pragma unroll
    for (int o = 16; o; o >>= 1) {
        sA += __shfl_xor_sync(0xFFFFFFFFu, sA, o);
        sB += __shfl_xor_sync(0xFFFFFFFFu, sB, o);
    }

    float pA0 = eA0 / sA, pA1 = eA1 / sA, pA2 = eA2 / sA;
    float pB0 = eB0 / sB, pB1 = eB1 / sB, pB2 = eB2 / sB;

    // probs out
    float* poA = out + OFF3 + (size_t)row0 * CC;
    float* poB = poA + CC;
    poA[lane]      = pA0;
    poA[lane + 32] = pA1;
    if (has2) poA[lane + 64] = pA2;
    poB[lane]      = pB0;
    poB[lane + 32] = pB1;
    if (has2) poB[lane + 64] = pB2;

    // argmax of probs, first-occurrence tie rule
    float bpA = pA0; int biA = lane;
    if (pA1 > bpA) { bpA = pA1; biA = lane + 32; }
    if (has2 && pA2 > bpA) { bpA = pA2; biA = lane + 64; }
    float bpB = pB0; int biB = lane;
    if (pB1 > bpB) { bpB = pB1; biB = lane + 32; }
    if (has2 && pB2 > bpB) { bpB = pB2; biB = lane + 64; }
    #pragma unroll
    for (int o = 16; o; o >>= 1) {
        float opA = __shfl_xor_sync(0xFFFFFFFFu, bpA, o);
        int   oiA = __shfl_xor_sync(0xFFFFFFFFu, biA, o);
        if (opA > bpA || (opA == bpA && oiA < biA)) { bpA = opA; biA = oiA; }
        float opB = __shfl_xor_sync(0xFFFFFFFFu, bpB, o);
        int   oiB = __shfl_xor_sync(0xFFFFFFFFu, biB, o);
        if (opB > bpB || (opB == bpB && oiB < biB)) { bpB = opB; biB = oiB; }
    }
    // all lanes now hold (bpA,biA,bpB,biB)

    const float kA = (biA != 0) ? 1.0f : 0.0f;
    const float kB = (biB != 0) ? 1.0f : 0.0f;

    // speculative cls_out = probs * k (bitwise probs when k=1, zeros when k=0)
    float* coA = out + OFF5 + (size_t)row0 * CC;
    float* coB = coA + CC;
    coA[lane]      = pA0 * kA;
    coA[lane + 32] = pA1 * kA;
    if (has2) coA[lane + 64] = pA2 * kA;
    coB[lane]      = pB0 * kB;
    coB[lane + 32] = pB1 * kB;
    if (has2) coB[lane + 64] = pB2 * kB;

    // scalar tail: lane 0 -> row0, lane 1 -> row1
    if (lane < 2) {
        const int   row = (lane == 0) ? row0 : row1;
        const int   cls = (lane == 0) ? biA  : biB;
        const float bp  = (lane == 0) ? bpA  : bpB;
        const float k   = (lane == 0) ? kA   : kB;
        const float red = read_reduction(redp);

        float4 nr = ((const float4*)nms_reg)[row];
        float rt = floorf(nr.x * red) / red;
        float rl = floorf(nr.y * red) / red;
        float rb = ceilf(nr.z * red) / red;
        float rr = ceilf(nr.w * red) / red;

        float4 rg = ((const float4*)rcnn_reg)[row];
        float4 adj;
        adj.x = rg.x + rt; adj.y = rg.y + rl; adj.z = rg.z + rb; adj.w = rg.w + rr;
        ((float4*)(out + OFF2))[row] = adj;

        float4 ro;
        ro.x = adj.x * k; ro.y = adj.y * k; ro.z = adj.z * k; ro.w = adj.w * k;
        ((float4*)(out + OFF4))[row] = ro;

        // passthrough copies
        ((float4*)(out + OFF0))[row] = nr;
        ((float2*)(out + OFF1))[row] = ((const float2*)nms_cls)[row];

        out[OFF6 + row] = k;   // speculative keep

        if (cls != 0) {
            // composite key: score desc, idx asc (ascending u64 order)
            unsigned sb = __float_as_uint(bp);
            unsigned so = (sb & 0x80000000u) ? ~sb : (sb | 0x80000000u);
            unsigned sdesc = ~so;
            int b = row / NN, n = row % NN;
            unsigned long long key = ((unsigned long long)sdesc << 32)
                                   | (unsigned long long)(unsigned)n;
            int bc = b * CC + cls;
            int pos = atomicAdd(&g_cnt[bc], 1);
            if (pos < CAP) g_bucket[(size_t)bc * CAP + pos] = key;
        }
    }
}

// ============================================================
// Kernel 2: per-(batch,class) greedy NMS + suppressed-row fixup.
// One warp per task. Cross-class IoU is exactly 0 due to
// CLASS_OFFSET, so per-class greedy NMS in (score desc, idx asc)
// order is identical to the reference's global greedy loop.
// Suppressed rows get their speculative outputs zeroed here.
// Also resets g_cnt for the next graph replay.
// ============================================================
#define NMS_WPB 8
__global__ __launch_bounds__(NMS_WPB * 32)
void nms_kernel(float* __restrict__ out)
{
    const int lane = threadIdx.x & 31;
    const int wib  = threadIdx.x >> 5;
    const int task = blockIdx.x * NMS_WPB + wib;
    if (task >= NTASK) return;

    const int b = task / (CC - 1);
    const int c = task % (CC - 1) + 1;
    const int bc = b * CC + c;

    int n = g_cnt[bc];
    if (lane == 0) g_cnt[bc] = 0;          // reset for next replay
    if (n > CAP) n = CAP;
    if (n <= 0) return;

    __shared__ unsigned long long s_raw [NMS_WPB][CAP];
    __shared__ float4             s_box [NMS_WPB][CAP];
    __shared__ unsigned short     s_sid [NMS_WPB][CAP];
    __shared__ unsigned char      s_keep[NMS_WPB][CAP];

    const unsigned long long* bk = g_bucket + (size_t)bc * CAP;
    for (int j = lane; j < n; j += 32) s_raw[wib][j] = bk[j];
    __syncwarp();

    const float off = (float)c * CLASS_OFFSET;

    // rank sort (keys unique via idx low bits -> perfect permutation)
    for (int j = lane; j < n; j += 32) {
        unsigned long long kj = s_raw[wib][j];
        int rank = 0;
        for (int kk = 0; kk < n; kk++) rank += (s_raw[wib][kk] < kj);
        int idx = (int)(kj & 0xFFFFFFFFu);
        float4 adj = ((const float4*)(out + OFF2))[b * NN + idx];
        float4 ob;
        ob.x = adj.x + off; ob.y = adj.y + off; ob.z = adj.z + off; ob.w = adj.w + off;
        s_sid[wib][rank]  = (unsigned short)idx;
        s_box[wib][rank]  = ob;
        s_keep[wib][rank] = 1;
    }
    __syncwarp();

    for (int i = 0; i < n - 1; i++) {
        if (s_keep[wib][i]) {
            float4 bi = s_box[wib][i];
            float areai = (bi.z - bi.x) * (bi.w - bi.y);
            for (int j = i + 1 + lane; j < n; j += 32) {
                if (s_keep[wib][j]) {
                    float4 bj = s_box[wib][j];
                    float areaj = (bj.z - bj.x) * (bj.w - bj.y);
                    float it = fmaxf(bi.x, bj.x);
                    float il = fmaxf(bi.y, bj.y);
                    float ib = fminf(bi.z, bj.z);
                    float ir = fminf(bi.w, bj.w);
                    float inter = fmaxf(ib - it, 0.0f) * fmaxf(ir - il, 0.0f);
                    float uni = areai + areaj - inter;
                    float iou = inter / fmaxf(uni, 1e-9f);
                    if (iou > IOU_THR) s_keep[wib][j] = 0;
                }
            }
        }
        __syncwarp();
    }

    // fixup: zero outputs of suppressed rows (few per task)
    for (int j = 0; j < n; j++) {
        if (!s_keep[wib][j]) {
            int row = b * NN + (int)s_sid[wib][j];
            float* co = out + OFF5 + (size_t)row * CC;
            for (int t = lane; t < CC; t += 32) co[t] = 0.0f;
            if (lane == 0) {
                float4 z; z.x = 0.0f; z.y = 0.0f; z.z = 0.0f; z.w = 0.0f;
                ((float4*)(out + OFF4))[row] = z;
                out[OFF6 + row] = 0.0f;
            }
        }
    }
}

extern "C" void kernel_launch(void* const* d_in, const int* in_sizes, int n_in,
                              void* d_out, int out_size)
{
    const float* nms_reg  = (const float*)d_in[0];
    const float* nms_cls  = (const float*)d_in[1];
    const float* rcnn_reg = (const float*)d_in[2];
    const float* rcnn_cls = (const float*)d_in[3];
    const void*  redp     = (n_in >= 5) ? d_in[4] : nullptr;
    float* out = (float*)d_out;
    (void)in_sizes; (void)out_size;

    // 8000 warps, 2 rows each
    const int warps = NROWS / 2;
    const int tpb = 256;
    const int blocks = (warps * 32 + tpb - 1) / tpb;   // 1000
    prep_kernel<<<blocks, tpb>>>(nms_reg, nms_cls, rcnn_reg, rcnn_cls, redp, out);

    nms_kernel<<<(NTASK + NMS_WPB - 1) / NMS_WPB, NMS_WPB * 32>>>(out);
}